// round 7
// baseline (speedup 1.0000x reference)
#include <cuda_runtime.h>
#include <cuda_bf16.h>

#define NN 100000
#define EE 600000
#define SCAN_BLK 1024
#define NBLK ((NN + SCAN_BLK - 1) / SCAN_BLK)   // 98

// ---------------- scratch (static device globals; no allocation) -------------
__device__ int   g_deg[NN];
__device__ int   g_off[NN + 1];
__device__ int   g_cur[NN];
__device__ float g_inv[NN];
__device__ int   g_src[EE];
__device__ int   g_bsum[NBLK];
__device__ float g_agg[(size_t)NN * 128];
__device__ float g_qr[(size_t)NN * 64];        // q (cols 0..31) | r (cols 32..63)
// W1 image, transposed [n][k] bf16, half 0 = hi, half 1 = lo  (k<128: W1l, else W1r)
__device__ __nv_bfloat16 g_w1t[2 * 128 * 256];
// W2 image for stage-2 frags: [img][n(64)][kb(64)] b32 (bf16x2 pairs along k=128)
__device__ unsigned g_w2i[2 * 64 * 64];
__device__ int   g_is64;

// ---------------- helpers ----------------------------------------------------
__device__ __forceinline__ int load_idx(const void* ei, long long pos, int is64) {
    if (is64) return (int)((const long long*)ei)[pos];
    return ((const int*)ei)[pos];
}
// pack two floats to bf16x2 (a -> low 16 bits, b -> high 16 bits)
__device__ __forceinline__ unsigned cvt_bf16x2(float a, float b) {
    unsigned r;
    asm("cvt.rn.bf16x2.f32 %0, %1, %2;" : "=r"(r) : "f"(b), "f"(a));
    return r;
}
__device__ __forceinline__ void mma16816(float* d, const unsigned* a, const unsigned* b) {
    asm volatile(
        "mma.sync.aligned.m16n8k16.row.col.f32.bf16.bf16.f32 "
        "{%0,%1,%2,%3}, {%4,%5,%6,%7}, {%8,%9}, {%0,%1,%2,%3};"
        : "+f"(d[0]), "+f"(d[1]), "+f"(d[2]), "+f"(d[3])
        : "r"(a[0]), "r"(a[1]), "r"(a[2]), "r"(a[3]), "r"(b[0]), "r"(b[1]));
}

// ---------------- dtype detection: int64 vs int32 edge_index -----------------
__global__ void k_detect(const unsigned long long* ei) {
    if (threadIdx.x == 0 && blockIdx.x == 0) {
        int is64 = 1;
        #pragma unroll 1
        for (int i = 0; i < 64; i++)
            if (ei[i] > 0xFFFFFFFFull) is64 = 0;
        g_is64 = is64;
    }
}

// ---------------- degree histogram -------------------------------------------
__global__ void k_zero_deg() {
    int i = blockIdx.x * blockDim.x + threadIdx.x;
    if (i < NN) g_deg[i] = 0;
}

__global__ void k_deg(const void* ei) {
    int e = blockIdx.x * blockDim.x + threadIdx.x;
    if (e < EE) {
        int is64 = g_is64;
        int dst = load_idx(ei, (long long)EE + e, is64);
        atomicAdd(&g_deg[dst], 1);
    }
}

// ---------------- chip-wide 3-phase exclusive scan ---------------------------
__global__ void k_scan_local() {
    __shared__ int warp_tot[32];
    int tid = threadIdx.x;
    int i = blockIdx.x * SCAN_BLK + tid;
    int lane = tid & 31, wid = tid >> 5;
    int v = (i < NN) ? g_deg[i] : 0;
    int inc = v;
    #pragma unroll
    for (int d = 1; d < 32; d <<= 1) {
        int t = __shfl_up_sync(0xFFFFFFFFu, inc, d);
        if (lane >= d) inc += t;
    }
    if (lane == 31) warp_tot[wid] = inc;
    __syncthreads();
    if (wid == 0) {
        int wv = warp_tot[lane];
        int winc = wv;
        #pragma unroll
        for (int d = 1; d < 32; d <<= 1) {
            int t = __shfl_up_sync(0xFFFFFFFFu, winc, d);
            if (lane >= d) winc += t;
        }
        warp_tot[lane] = winc - wv;
        if (lane == 31) g_bsum[blockIdx.x] = winc;
    }
    __syncthreads();
    if (i < NN) g_off[i] = warp_tot[wid] + inc - v;
}

__global__ void k_scan_bsum() {
    int lane = threadIdx.x;
    int carry = 0;
    for (int base = 0; base < NBLK; base += 32) {
        int idx = base + lane;
        int v = (idx < NBLK) ? g_bsum[idx] : 0;
        int inc = v;
        #pragma unroll
        for (int d = 1; d < 32; d <<= 1) {
            int t = __shfl_up_sync(0xFFFFFFFFu, inc, d);
            if (lane >= d) inc += t;
        }
        if (idx < NBLK) g_bsum[idx] = carry + inc - v;
        carry += __shfl_sync(0xFFFFFFFFu, inc, 31);
    }
    if (lane == 0) g_off[NN] = EE;
}

__global__ void k_scan_apply() {
    int i = blockIdx.x * SCAN_BLK + threadIdx.x;
    if (i < NN) {
        int excl = g_off[i] + g_bsum[blockIdx.x];
        g_off[i] = excl;
        g_cur[i] = excl;
        g_inv[i] = 1.0f / (float)max(g_deg[i], 1);
    }
}

// ---------------- CSR placement ----------------------------------------------
__global__ void k_fill(const void* ei) {
    int e = blockIdx.x * blockDim.x + threadIdx.x;
    if (e < EE) {
        int is64 = g_is64;
        int dst = load_idx(ei, (long long)EE + e, is64);
        int src = load_idx(ei, e, is64);
        int pos = atomicAdd(&g_cur[dst], 1);
        g_src[pos] = src;
    }
}

// ---------------- gather aggregation (layer 1): warp per node -----------------
__global__ void k_agg(const float* __restrict__ feat, float* __restrict__ agg) {
    int w = (blockIdx.x * blockDim.x + threadIdx.x) >> 5;
    int lane = threadIdx.x & 31;
    if (w >= NN) return;
    int s = g_off[w], e = g_off[w + 1];
    float4 acc = make_float4(0.f, 0.f, 0.f, 0.f);
    for (int i = s; i < e; i++) {
        int sn = g_src[i];
        float4 v = __ldg((const float4*)(feat + (size_t)sn * 128 + lane * 4));
        acc.x += v.x; acc.y += v.y; acc.z += v.z; acc.w += v.w;
    }
    float iv = g_inv[w];
    acc.x *= iv; acc.y *= iv; acc.z *= iv; acc.w *= iv;
    *((float4*)(agg + (size_t)w * 128 + lane * 4)) = acc;
}

// ---------------- weight prep -------------------------------------------------
// W1: transposed [n][256] bf16 hi/lo (k<128 -> W1l[k][n], else W1r[k-128][n])
__global__ void k_prepw1(const float* __restrict__ Wl, const float* __restrict__ Wr) {
    int idx = blockIdx.x * blockDim.x + threadIdx.x;
    const int total = 128 * 256;
    if (idx >= 2 * total) return;
    int half = idx >= total;
    int rem = half ? idx - total : idx;
    int n = rem >> 8;
    int k = rem & 255;
    float w = (k < 128) ? Wl[k * 128 + n] : Wr[(k - 128) * 128 + n];
    __nv_bfloat16 hi = __float2bfloat16(w);
    __nv_bfloat16 val = half ? __float2bfloat16(w - __bfloat162float(hi)) : hi;
    g_w1t[(size_t)half * total + n * 256 + k] = val;
}

// W2 image: [img][n][kb] b32; n<32 -> W2l[k][n], n>=32 -> W2r[k][n-32]; k=2kb,2kb+1
__global__ void k_prepw2(const float* __restrict__ W2l, const float* __restrict__ W2r) {
    int idx = blockIdx.x * blockDim.x + threadIdx.x;   // 2*64*64
    if (idx >= 2 * 64 * 64) return;
    int img = idx >> 12;
    int rem = idx & 4095;
    int n = rem >> 6;
    int kb = rem & 63;
    const float* W = (n < 32) ? W2l : W2r;
    int c = (n < 32) ? n : n - 32;
    float w0 = W[(2 * kb) * 32 + c];
    float w1 = W[(2 * kb + 1) * 32 + c];
    if (img == 0) {
        g_w2i[idx] = cvt_bf16x2(__bfloat162float(__float2bfloat16(w0)),
                                __bfloat162float(__float2bfloat16(w1)));
        // store rounded values exactly: pack via cvt (round-to-nearest is fine)
        g_w2i[idx] = cvt_bf16x2(w0, w1);
    } else {
        float h0 = __bfloat162float(__float2bfloat16(w0));
        float h1 = __bfloat162float(__float2bfloat16(w1));
        g_w2i[idx] = cvt_bf16x2(w0 - h0, w1 - h1);
    }
}

// ---------------- fused GEMM1 + GEMM2 ----------------------------------------
// stage1: h = relu([agg|x] @ W1' + b1)   (in registers, never stored)
// stage2: [q|r] = h @ [W2l|W2r]          (A-frags straight from stage1 accums)
// writes g_qr[row][0..63].
#define SSTR 20
__global__ void __launch_bounds__(256)
k_fused(const float* __restrict__ Aagg, const float* __restrict__ Ax,
        const __nv_bfloat16* __restrict__ Wt, const float* __restrict__ bias1,
        float* __restrict__ qr) {
    __shared__ union SU {
        struct { unsigned A[2][128 * SSTR]; unsigned B[2][128 * SSTR]; } s;
        float red[4][32 * 66];
    } su;

    const int tid = threadIdx.x;
    const int wid = tid >> 5, lane = tid & 31;
    const int lr = lane >> 2, lc = lane & 3;
    const int row0 = blockIdx.x * 128;
    const int warp_n = wid & 1;          // 2 warps along N (WN=64)
    const int warp_m = wid >> 1;         // 4 warps along M (WM=32)

    const unsigned* Bt32 = (const unsigned*)Wt;
    constexpr int BHALF = 128 * 128;     // b32 offset of lo image

    float acc[2][8][4];
    #pragma unroll
    for (int t = 0; t < 2; t++)
        #pragma unroll
        for (int u = 0; u < 8; u++)
            #pragma unroll
            for (int q = 0; q < 4; q++) acc[t][u][q] = 0.f;

    // ================= stage 1 mainloop (K=256, 8 chunks of 32) ==============
    #pragma unroll 1
    for (int kc = 0; kc < 8; kc++) {
        const int k0 = kc * 32;
        const float* Abase = (k0 < 128) ? (Aagg + k0) : (Ax + (k0 - 128));
        #pragma unroll
        for (int t = 0; t < 4; t++) {
            int id = tid + t * 256;
            int row = id >> 3;
            int c4 = id & 7;
            int rg = row0 + row;
            float4 f = (rg < NN)
                ? __ldg((const float4*)(Abase + (size_t)rg * 128 + c4 * 4))
                : make_float4(0.f, 0.f, 0.f, 0.f);
            float hx = __bfloat162float(__float2bfloat16(f.x));
            float hy = __bfloat162float(__float2bfloat16(f.y));
            float hz = __bfloat162float(__float2bfloat16(f.z));
            float hw = __bfloat162float(__float2bfloat16(f.w));
            int p = row * SSTR + c4 * 2;
            su.s.A[0][p]     = cvt_bf16x2(f.x, f.y);
            su.s.A[0][p + 1] = cvt_bf16x2(f.z, f.w);
            su.s.A[1][p]     = cvt_bf16x2(f.x - hx, f.y - hy);
            su.s.A[1][p + 1] = cvt_bf16x2(f.z - hz, f.w - hw);
        }
        #pragma unroll
        for (int id = tid; id < 128 * 16; id += 256) {
            int n = id >> 4;
            int j = id & 15;
            int srcp = n * 128 + (k0 >> 1) + j;
            su.s.B[0][n * SSTR + j] = __ldg(&Bt32[srcp]);
            su.s.B[1][n * SSTR + j] = __ldg(&Bt32[BHALF + srcp]);
        }
        __syncthreads();

        #pragma unroll
        for (int kh = 0; kh < 2; kh++) {
            const int base = kh * 8;
            unsigned ah[2][4], al[2][4];
            #pragma unroll
            for (int t = 0; t < 2; t++) {
                int r = warp_m * 32 + t * 16 + lr;
                int p0 = r * SSTR + base + lc;
                int p1 = (r + 8) * SSTR + base + lc;
                ah[t][0] = su.s.A[0][p0]; ah[t][1] = su.s.A[0][p1];
                ah[t][2] = su.s.A[0][p0 + 4]; ah[t][3] = su.s.A[0][p1 + 4];
                al[t][0] = su.s.A[1][p0]; al[t][1] = su.s.A[1][p1];
                al[t][2] = su.s.A[1][p0 + 4]; al[t][3] = su.s.A[1][p1 + 4];
            }
            unsigned bh[8][2], bl[8][2];
            #pragma unroll
            for (int u = 0; u < 8; u++) {
                int n = warp_n * 64 + u * 8 + lr;
                int p = n * SSTR + base + lc;
                bh[u][0] = su.s.B[0][p]; bh[u][1] = su.s.B[0][p + 4];
                bl[u][0] = su.s.B[1][p]; bl[u][1] = su.s.B[1][p + 4];
            }
            #pragma unroll
            for (int t = 0; t < 2; t++)
                #pragma unroll
                for (int u = 0; u < 8; u++) {
                    mma16816(acc[t][u], ah[t], bh[u]);
                    mma16816(acc[t][u], al[t], bh[u]);
                    mma16816(acc[t][u], ah[t], bl[u]);
                }
        }
        __syncthreads();
    }

    // ---- bias1 + relu -> h (in place) ---------------------------------------
    #pragma unroll
    for (int u = 0; u < 8; u++) {
        int c = warp_n * 64 + u * 8 + lc * 2;
        float b0 = __ldg(&bias1[c]), b1v = __ldg(&bias1[c + 1]);
        #pragma unroll
        for (int t = 0; t < 2; t++) {
            acc[t][u][0] = fmaxf(acc[t][u][0] + b0, 0.f);
            acc[t][u][1] = fmaxf(acc[t][u][1] + b1v, 0.f);
            acc[t][u][2] = fmaxf(acc[t][u][2] + b0, 0.f);
            acc[t][u][3] = fmaxf(acc[t][u][3] + b1v, 0.f);
        }
    }

    // ================= stage 2: [q|r] = h @ W2 (K-slice = warp_n's 64 cols) ==
    float acc2[2][8][4];
    #pragma unroll
    for (int t = 0; t < 2; t++)
        #pragma unroll
        for (int u = 0; u < 8; u++)
            #pragma unroll
            for (int q = 0; q < 4; q++) acc2[t][u][q] = 0.f;

    #pragma unroll
    for (int ks = 0; ks < 4; ks++) {
        // A-frags from h registers (hi/lo split)
        unsigned ah[2][4], al[2][4];
        #pragma unroll
        for (int t = 0; t < 2; t++)
            #pragma unroll
            for (int q = 0; q < 4; q++) {
                int u = 2 * ks + (q >> 1);
                int o = (q & 1) * 2;
                float v0 = acc[t][u][o], v1 = acc[t][u][o + 1];
                float h0 = __bfloat162float(__float2bfloat16(v0));
                float h1 = __bfloat162float(__float2bfloat16(v1));
                ah[t][q] = cvt_bf16x2(v0, v1);
                al[t][q] = cvt_bf16x2(v0 - h0, v1 - h1);
            }
        int kb0 = warp_n * 32 + ks * 8 + lc;
        #pragma unroll
        for (int u2 = 0; u2 < 8; u2++) {
            int n = u2 * 8 + lr;
            unsigned bh[2], bl[2];
            bh[0] = __ldg(&g_w2i[n * 64 + kb0]);
            bh[1] = __ldg(&g_w2i[n * 64 + kb0 + 4]);
            bl[0] = __ldg(&g_w2i[4096 + n * 64 + kb0]);
            bl[1] = __ldg(&g_w2i[4096 + n * 64 + kb0 + 4]);
            #pragma unroll
            for (int t = 0; t < 2; t++) {
                mma16816(acc2[t][u2], ah[t], bh);
                mma16816(acc2[t][u2], al[t], bh);
                mma16816(acc2[t][u2], ah[t], bl);
            }
        }
    }

    // ---- cross-warp reduction (warp_n 1 -> smem, warp_n 0 adds + writes) ----
    __syncthreads();   // everyone past last smem use of stage 1
    if (warp_n == 1) {
        #pragma unroll
        for (int t = 0; t < 2; t++)
            #pragma unroll
            for (int u2 = 0; u2 < 8; u2++) {
                int r = t * 16 + lr;
                int c = u2 * 8 + lc * 2;
                *(float2*)&su.red[warp_m][r * 66 + c] =
                    make_float2(acc2[t][u2][0], acc2[t][u2][1]);
                *(float2*)&su.red[warp_m][(r + 8) * 66 + c] =
                    make_float2(acc2[t][u2][2], acc2[t][u2][3]);
            }
    }
    __syncthreads();
    if (warp_n == 0) {
        #pragma unroll
        for (int t = 0; t < 2; t++)
            #pragma unroll
            for (int u2 = 0; u2 < 8; u2++) {
                int r = t * 16 + lr;
                int c = u2 * 8 + lc * 2;
                float2 p0 = *(float2*)&su.red[warp_m][r * 66 + c];
                float2 p1 = *(float2*)&su.red[warp_m][(r + 8) * 66 + c];
                int rg0 = row0 + warp_m * 32 + r;
                int rg1 = rg0 + 8;
                if (rg0 < NN)
                    *(float2*)&qr[(size_t)rg0 * 64 + c] =
                        make_float2(acc2[t][u2][0] + p0.x, acc2[t][u2][1] + p0.y);
                if (rg1 < NN)
                    *(float2*)&qr[(size_t)rg1 * 64 + c] =
                        make_float2(acc2[t][u2][2] + p1.x, acc2[t][u2][3] + p1.y);
            }
    }
}

// ---------------- final: out = inv_deg * segsum(q[src]) + r + b2 -------------
__global__ void k_out(const float* __restrict__ qr, const float* __restrict__ b2,
                      float* __restrict__ outp) {
    int w = (blockIdx.x * blockDim.x + threadIdx.x) >> 5;
    int lane = threadIdx.x & 31;
    if (w >= NN) return;
    int s = g_off[w], e = g_off[w + 1];
    float acc = 0.f;
    for (int i = s; i < e; i++) {
        int sn = g_src[i];
        acc += __ldg(&qr[(size_t)sn * 64 + lane]);
    }
    float r = __ldg(&qr[(size_t)w * 64 + 32 + lane]);
    outp[(size_t)w * 32 + lane] = g_inv[w] * acc + r + __ldg(&b2[lane]);
}

// ---------------- launch ------------------------------------------------------
extern "C" void kernel_launch(void* const* d_in, const int* in_sizes, int n_in,
                              void* d_out, int out_size) {
    const float* x   = (const float*)d_in[0];
    const void*  ei  = d_in[1];
    const float* W1l = (const float*)d_in[2];
    const float* b1  = (const float*)d_in[3];
    const float* W1r = (const float*)d_in[4];
    const float* W2l = (const float*)d_in[5];
    const float* b2  = (const float*)d_in[6];
    const float* W2r = (const float*)d_in[7];
    float* out = (float*)d_out;

    float *agg, *qr;
    __nv_bfloat16* w1t;
    cudaGetSymbolAddress((void**)&agg, g_agg);
    cudaGetSymbolAddress((void**)&qr, g_qr);
    cudaGetSymbolAddress((void**)&w1t, g_w1t);

    k_detect<<<1, 32>>>((const unsigned long long*)ei);
    k_zero_deg<<<(NN + 255) / 256, 256>>>();
    k_prepw1<<<(2 * 128 * 256 + 255) / 256, 256>>>(W1l, W1r);
    k_prepw2<<<(2 * 64 * 64 + 255) / 256, 256>>>(W2l, W2r);
    k_deg<<<(EE + 255) / 256, 256>>>(ei);
    k_scan_local<<<NBLK, SCAN_BLK>>>();
    k_scan_bsum<<<1, 32>>>();
    k_scan_apply<<<NBLK, SCAN_BLK>>>();
    k_fill<<<(EE + 255) / 256, 256>>>(ei);

    // layer 1 aggregation
    k_agg<<<(NN * 32 + 255) / 256, 256>>>(x, agg);
    // fused layer-1 GEMM + relu + layer-2 GEMM  -> q | r
    k_fused<<<(NN + 127) / 128, 256>>>(agg, x, w1t, b1, qr);
    // final aggregation of q + bias
    k_out<<<(NN * 32 + 255) / 256, 256>>>(qr, b2, out);
}